// round 10
// baseline (speedup 1.0000x reference)
#include <cuda_runtime.h>
#include <cuda_fp16.h>
#include <math.h>
#include <mma.h>
using namespace nvcuda;

#define NN 50000
#define EE 800000
#define DD 96
#define CC 40
#define NITE 8
#define SMOOTH 0.5f

#define NBANDS ((NN + 15) / 16)   // 3125 (NN % 16 == 0)
#define NTASKS (NBANDS * 2)       // N-split GEMM warp tasks
#define LDW 104                   // padded half ld for W smem
#define SUP_LD 128                // padded support row stride (halves) -> 256B rows

// ---------------- scratch (device globals; no allocation allowed) ------------
__device__ float  g_h[NN * DD];            // fp32 master features
__device__ __half g_h16[NN * DD];          // fp16 mirror (tensor-core A operand)
__device__ __half g_W16[DD * DD];          // fp16 W_gc
__device__ __half g_support16[NN * SUP_LD];// GEMM out (fp16, padded rows)
__device__ int    g_count[NN];             // zero at kernel_launch entry (invariant)
__device__ int    g_rowstart[NN + 1];
__device__ int    g_fill[NN];
__device__ int2   g_edge[EE];              // CSR: {src col, f32 val}

// packed f32x2 FMA
__device__ __forceinline__ void ffma2f(float2& d, float2 a, float2 b) {
    unsigned long long dd = *(unsigned long long*)&d;
    asm("fma.rn.f32x2 %0, %1, %2, %0;"
        : "+l"(dd) : "l"(*(unsigned long long*)&a), "l"(*(unsigned long long*)&b));
    d = *(float2*)&dd;
}

// ---------------- init h/h16/W16 + edge histogram (counts pre-zeroed) --------
__global__ void init_hist_kernel(const float* __restrict__ x,
                                 const float* __restrict__ W,
                                 const int* __restrict__ erow) {
    int i = blockIdx.x * blockDim.x + threadIdx.x;
    if (i < NN * DD) { float v = x[i]; g_h[i] = v; g_h16[i] = __float2half(v); }
    if (i < DD * DD) g_W16[i] = __float2half(W[i]);
    if (i < EE) atomicAdd(&g_count[erow[i]], 1);
}

__global__ void scan_kernel() {
    __shared__ int part[1024];
    const int CH = (NN + 1023) / 1024;
    int t = threadIdx.x;
    int begin = t * CH;
    int end = begin + CH; if (end > NN) end = NN;
    int s = 0;
    for (int i = begin; i < end; ++i) s += g_count[i];
    part[t] = s;
    __syncthreads();
    for (int off = 1; off < 1024; off <<= 1) {
        int v = (t >= off) ? part[t - off] : 0;
        __syncthreads();
        part[t] += v;
        __syncthreads();
    }
    int running = (t == 0) ? 0 : part[t - 1];
    for (int i = begin; i < end; ++i) {
        g_rowstart[i] = running;
        g_fill[i] = running;
        running += g_count[i];
    }
    if (t == 1023) g_rowstart[NN] = running;  // == EE
}

__global__ void fill_kernel(const int* __restrict__ erow,
                            const int* __restrict__ ecol,
                            const float* __restrict__ ev) {
    int e = blockIdx.x * blockDim.x + threadIdx.x;
    if (e < EE) {
        int r = erow[e];
        int p = atomicAdd(&g_fill[r], 1);
        g_edge[p] = make_int2(ecol[e], __float_as_int(ev[e]));
    }
}

// ---------------- GEMM: support16 = h16 @ W16 (tensor cores, N-split) --------
// Warp task = 16 rows x 48 cols (half the N range) -> 6250 tasks, 782 blocks.
__global__ void __launch_bounds__(256) gemm_kernel() {
    __shared__ __half Ws[DD * LDW];   // 19968 B
    int tid = threadIdx.x, wid = tid >> 5;
    int task = blockIdx.x * 8 + wid;

    for (int i = tid; i < DD * DD / 8; i += 256) {
        int r = (i * 8) / DD, c = (i * 8) % DD;
        *(uint4*)&Ws[r * LDW + c] = *(const uint4*)&g_W16[r * DD + c];
    }
    __syncthreads();
    if (task >= NTASKS) return;
    int band = task >> 1;
    int nh = task & 1;               // which 48-col half

    wmma::fragment<wmma::matrix_a, 16, 16, 16, __half, wmma::row_major> af[6];
    const __half* Abase = g_h16 + (size_t)band * 16 * DD;
#pragma unroll
    for (int k = 0; k < 6; ++k)
        wmma::load_matrix_sync(af[k], Abase + k * 16, DD);

    wmma::fragment<wmma::accumulator, 16, 16, 16, __half> acc[3];
#pragma unroll
    for (int n = 0; n < 3; ++n) wmma::fill_fragment(acc[n], __float2half(0.f));

#pragma unroll
    for (int k = 0; k < 6; ++k) {
#pragma unroll
        for (int n = 0; n < 3; ++n) {
            wmma::fragment<wmma::matrix_b, 16, 16, 16, __half, wmma::row_major> bf;
            wmma::load_matrix_sync(bf, Ws + (k * 16) * LDW + nh * 48 + n * 16, LDW);
            wmma::mma_sync(acc[n], af[k], bf, acc[n]);
        }
    }

    __half* Obase = g_support16 + (size_t)band * 16 * SUP_LD + nh * 48;
#pragma unroll
    for (int n = 0; n < 3; ++n)
        wmma::store_matrix_sync(Obase + n * 16, acc[n], SUP_LD, wmma::mem_row_major);
}

// ---------------- aggregation + smooth + ReLU --------------------------------
// One warp per row, one edge at a time: 24 lanes gather the edge's support row
// contiguously (lane L -> features 4L..4L+3), 2 wavefronts per edge (vs 12).
// Edge metadata batched 8-wide, broadcast via shfl; 8 row-loads in flight.
__global__ void __launch_bounds__(256) agg_kernel(const float* __restrict__ b) {
    int warp = (blockIdx.x * blockDim.x + threadIdx.x) >> 5;
    int lane = threadIdx.x & 31;
    if (warp >= NN) return;

    int j0 = g_rowstart[warp];
    int j1 = g_rowstart[warp + 1];

    float2 a0 = make_float2(0.f, 0.f);   // features 4L, 4L+1
    float2 a1 = make_float2(0.f, 0.f);   // features 4L+2, 4L+3

    int j = j0;
    for (; j + 8 <= j1; j += 8) {
        int2 m = make_int2(0, 0);
        if (lane < 8) m = __ldg(&g_edge[j + lane]);
        uint2 d[8];
        float vs[8];
#pragma unroll
        for (int t = 0; t < 8; ++t) {
            int col = __shfl_sync(0xffffffffu, m.x, t);
            vs[t] = __int_as_float(__shfl_sync(0xffffffffu, m.y, t));
            d[t] = (lane < 24)
                 ? __ldg((const uint2*)(g_support16 + (size_t)col * SUP_LD) + lane)
                 : make_uint2(0u, 0u);
        }
#pragma unroll
        for (int t = 0; t < 8; ++t) {
            float2 vv = make_float2(vs[t], vs[t]);
            float2 f0 = __half22float2(*(__half2*)&d[t].x);
            float2 f1 = __half22float2(*(__half2*)&d[t].y);
            ffma2f(a0, f0, vv);
            ffma2f(a1, f1, vv);
        }
    }
    // tail (< 8 edges)
    int rem = j1 - j;
    if (rem > 0) {
        int2 m = make_int2(0, 0);
        if (lane < rem) m = __ldg(&g_edge[j + lane]);
        for (int t = 0; t < rem; ++t) {
            int col = __shfl_sync(0xffffffffu, m.x, t);
            float v = __int_as_float(__shfl_sync(0xffffffffu, m.y, t));
            if (lane < 24) {
                uint2 d = __ldg((const uint2*)(g_support16 + (size_t)col * SUP_LD) + lane);
                float2 vv = make_float2(v, v);
                float2 f0 = __half22float2(*(__half2*)&d.x);
                float2 f1 = __half22float2(*(__half2*)&d.y);
                ffma2f(a0, f0, vv);
                ffma2f(a1, f1, vv);
            }
        }
    }

    if (lane < 24) {
        int off = 4 * lane;
        float* hrow = g_h + (size_t)warp * DD;
        float4 hv = *(float4*)&hrow[off];
        float4 bv = *(const float4*)&b[off];
        hv.x = fmaxf(SMOOTH * hv.x + (1.f - SMOOTH) * (a0.x + bv.x), 0.f);
        hv.y = fmaxf(SMOOTH * hv.y + (1.f - SMOOTH) * (a0.y + bv.y), 0.f);
        hv.z = fmaxf(SMOOTH * hv.z + (1.f - SMOOTH) * (a1.x + bv.z), 0.f);
        hv.w = fmaxf(SMOOTH * hv.w + (1.f - SMOOTH) * (a1.y + bv.w), 0.f);
        *(float4*)&hrow[off] = hv;
        __half2 p0 = __floats2half2_rn(hv.x, hv.y);
        __half2 p1 = __floats2half2_rn(hv.z, hv.w);
        uint2 u; u.x = *(unsigned*)&p0; u.y = *(unsigned*)&p1;
        *(uint2*)&g_h16[(size_t)warp * DD + off] = u;
    }
}

// ---------------- final: logits + log_softmax; re-zero counts for next replay
__global__ void __launch_bounds__(256) out_kernel(const float* __restrict__ Wl,
                                                  float* __restrict__ out) {
    __shared__ float Ws2[DD * CC];
    __shared__ float Hs[32 * DD];
    __shared__ float Ls[32 * CC];
    int tid = threadIdx.x;
    int row0 = blockIdx.x * 32;

    int gz = blockIdx.x * blockDim.x + tid;
    if (gz < NN) g_count[gz] = 0;

    for (int i = tid; i < DD * CC; i += 256) Ws2[i] = Wl[i];
    for (int i = tid; i < 32 * DD; i += 256) {
        int r = row0 + i / DD;
        Hs[i] = (r < NN) ? g_h[r * DD + (i % DD)] : 0.f;
    }
    __syncthreads();

    for (int o = tid; o < 32 * CC; o += 256) {
        int r = o / CC, c = o % CC;
        float a = 0.f;
#pragma unroll 4
        for (int k = 0; k < DD; ++k) a += Hs[r * DD + k] * Ws2[k * CC + c];
        Ls[o] = a;
    }
    __syncthreads();

    if (tid < 32) {
        int r = row0 + tid;
        if (r < NN) {
            float m = -1e30f;
#pragma unroll
            for (int c = 0; c < CC; ++c) m = fmaxf(m, Ls[tid * CC + c]);
            float s = 0.f;
#pragma unroll
            for (int c = 0; c < CC; ++c) s += expf(Ls[tid * CC + c] - m);
            float lse = m + logf(s);
#pragma unroll
            for (int c = 0; c < CC; ++c) out[r * CC + c] = Ls[tid * CC + c] - lse;
        }
    }
}

// ---------------- launch ------------------------------------------------------
extern "C" void kernel_launch(void* const* d_in, const int* in_sizes, int n_in,
                              void* d_out, int out_size) {
    (void)in_sizes; (void)n_in; (void)out_size;
    const float* x    = (const float*)d_in[0];
    const int*   erow = (const int*)d_in[1];
    const int*   ecol = (const int*)d_in[2];
    const float* ev   = (const float*)d_in[3];
    const float* Wgc  = (const float*)d_in[4];
    const float* bgc  = (const float*)d_in[5];
    const float* Wlin = (const float*)d_in[6];
    float* out = (float*)d_out;

    init_hist_kernel<<<(NN * DD + 255) / 256, 256>>>(x, Wgc, erow);
    scan_kernel<<<1, 1024>>>();
    fill_kernel<<<(EE + 255) / 256, 256>>>(erow, ecol, ev);

    for (int it = 0; it < NITE; ++it) {
        gemm_kernel<<<(NTASKS + 7) / 8, 256>>>();
        agg_kernel<<<(NN * 32 + 255) / 256, 256>>>(bgc);
    }

    out_kernel<<<(NN + 31) / 32, 256>>>(Wlin, out);
}

// round 11
// speedup vs baseline: 1.0659x; 1.0659x over previous
#include <cuda_runtime.h>
#include <cuda_fp16.h>
#include <math.h>
#include <mma.h>
using namespace nvcuda;

#define NN 50000
#define EE 800000
#define DD 96
#define CC 40
#define NITE 8
#define SMOOTH 0.5f

#define NBANDS ((NN + 15) / 16)   // 3125 (NN % 16 == 0)
#define LDW 104                   // padded half ld for W smem
#define LDA 104                   // padded half ld for A smem (208B rows, 16B aligned)

// ---------------- scratch (device globals; no allocation allowed) ------------
__device__ float  g_h[NN * DD];            // fp32 master features
__device__ __half g_h16[NN * DD];          // fp16 mirror (tensor-core A operand)
__device__ __half g_W16[DD * DD];          // fp16 W_gc
__device__ __half g_support16[NN * DD];    // GEMM out (fp16) / agg gather in
__device__ int    g_count[NN];             // zero at kernel_launch entry (invariant)
__device__ int    g_rowstart[NN + 1];
__device__ int    g_fill[NN];
__device__ int2   g_edge[EE];              // CSR: {src col, f32 val}

// packed f32x2 FMA
__device__ __forceinline__ void ffma2f(float2& d, float2 a, float2 b) {
    unsigned long long dd = *(unsigned long long*)&d;
    asm("fma.rn.f32x2 %0, %1, %2, %0;"
        : "+l"(dd) : "l"(*(unsigned long long*)&a), "l"(*(unsigned long long*)&b));
    d = *(float2*)&dd;
}

// ---------------- init h/h16/W16 + edge histogram (counts pre-zeroed) --------
__global__ void init_hist_kernel(const float* __restrict__ x,
                                 const float* __restrict__ W,
                                 const int* __restrict__ erow) {
    int i = blockIdx.x * blockDim.x + threadIdx.x;
    if (i < NN * DD) { float v = x[i]; g_h[i] = v; g_h16[i] = __float2half(v); }
    if (i < DD * DD) g_W16[i] = __float2half(W[i]);
    if (i < EE) atomicAdd(&g_count[erow[i]], 1);
}

__global__ void scan_kernel() {
    __shared__ int part[1024];
    const int CH = (NN + 1023) / 1024;
    int t = threadIdx.x;
    int begin = t * CH;
    int end = begin + CH; if (end > NN) end = NN;
    int s = 0;
    for (int i = begin; i < end; ++i) s += g_count[i];
    part[t] = s;
    __syncthreads();
    for (int off = 1; off < 1024; off <<= 1) {
        int v = (t >= off) ? part[t - off] : 0;
        __syncthreads();
        part[t] += v;
        __syncthreads();
    }
    int running = (t == 0) ? 0 : part[t - 1];
    for (int i = begin; i < end; ++i) {
        g_rowstart[i] = running;
        g_fill[i] = running;
        running += g_count[i];
    }
    if (t == 1023) g_rowstart[NN] = running;  // == EE
}

__global__ void fill_kernel(const int* __restrict__ erow,
                            const int* __restrict__ ecol,
                            const float* __restrict__ ev) {
    int e = blockIdx.x * blockDim.x + threadIdx.x;
    if (e < EE) {
        int r = erow[e];
        int p = atomicAdd(&g_fill[r], 1);
        g_edge[p] = make_int2(ecol[e], __float_as_int(ev[e]));
    }
}

// ---------------- GEMM: support16 = h16 @ W16 (tensor cores) -----------------
// 8 warps/block, 128 rows/block. A tile staged into smem with coalesced uint4
// loads, then warp fragments come via LDSM (smem load_matrix_sync). B in smem.
// fp16 accumulators stored directly to g_support16 (ld = DD).
__global__ void __launch_bounds__(256) gemm_kernel() {
    __shared__ __half Ws[DD * LDW];      // 19968 B
    __shared__ __half As[128 * LDA];     // 26624 B  (total 46592 B static)
    int tid = threadIdx.x, wid = tid >> 5;
    int row0 = blockIdx.x * 128;

    for (int i = tid; i < DD * DD / 8; i += 256) {
        int r = (i * 8) / DD, c = (i * 8) % DD;
        *(uint4*)&Ws[r * LDW + c] = *(const uint4*)&g_W16[r * DD + c];
    }
    // stage A: 128 rows x 12 uint4 (96 halves), coalesced, row-guarded
    for (int i = tid; i < 128 * 12; i += 256) {
        int r = i / 12, c = i % 12;
        int gr = row0 + r;
        uint4 v = make_uint4(0u, 0u, 0u, 0u);
        if (gr < NN) v = *(const uint4*)&g_h16[(size_t)gr * DD + c * 8];
        *(uint4*)&As[r * LDA + c * 8] = v;
    }
    __syncthreads();

    int band = blockIdx.x * 8 + wid;
    if (band >= NBANDS) return;

    // A fragments from smem (LDSM path)
    wmma::fragment<wmma::matrix_a, 16, 16, 16, __half, wmma::row_major> af[6];
    const __half* Abase = As + wid * 16 * LDA;
#pragma unroll
    for (int k = 0; k < 6; ++k)
        wmma::load_matrix_sync(af[k], Abase + k * 16, LDA);

    wmma::fragment<wmma::accumulator, 16, 16, 16, __half> acc[6];
#pragma unroll
    for (int n = 0; n < 6; ++n) wmma::fill_fragment(acc[n], __float2half(0.f));

#pragma unroll
    for (int k = 0; k < 6; ++k) {
#pragma unroll
        for (int n = 0; n < 6; ++n) {
            wmma::fragment<wmma::matrix_b, 16, 16, 16, __half, wmma::row_major> bf;
            wmma::load_matrix_sync(bf, Ws + (k * 16) * LDW + n * 16, LDW);
            wmma::mma_sync(acc[n], af[k], bf, acc[n]);
        }
    }

    __half* Obase = g_support16 + (size_t)band * 16 * DD;
#pragma unroll
    for (int n = 0; n < 6; ++n)
        wmma::store_matrix_sync(Obase + n * 16, acc[n], DD, wmma::mem_row_major);
}

// ---------------- aggregation + smooth + ReLU (R5 body, fp16 gathers) --------
__global__ void __launch_bounds__(256) agg_kernel(const float* __restrict__ b) {
    int warp = (blockIdx.x * blockDim.x + threadIdx.x) >> 5;
    int lane = threadIdx.x & 31;
    if (warp >= NN) return;
    int grp = lane >> 3;
    int sub = lane & 7;

    int j0 = g_rowstart[warp];
    int j1 = g_rowstart[warp + 1];

    float2 acc[6];
#pragma unroll
    for (int i = 0; i < 6; ++i) acc[i] = make_float2(0.f, 0.f);

    for (int j = j0 + grp; j < j1; j += 4) {
        int2 e = __ldg(&g_edge[j]);
        float v = __int_as_float(e.y);
        float2 vv = make_float2(v, v);
        const uint2* s = (const uint2*)(g_support16 + (size_t)e.x * DD);
        uint2 d0 = __ldg(&s[sub]);
        uint2 d1 = __ldg(&s[8 + sub]);
        uint2 d2 = __ldg(&s[16 + sub]);
        float2 f;
        f = __half22float2(*(__half2*)&d0.x); ffma2f(acc[0], f, vv);
        f = __half22float2(*(__half2*)&d0.y); ffma2f(acc[1], f, vv);
        f = __half22float2(*(__half2*)&d1.x); ffma2f(acc[2], f, vv);
        f = __half22float2(*(__half2*)&d1.y); ffma2f(acc[3], f, vv);
        f = __half22float2(*(__half2*)&d2.x); ffma2f(acc[4], f, vv);
        f = __half22float2(*(__half2*)&d2.y); ffma2f(acc[5], f, vv);
    }

#pragma unroll
    for (int i = 0; i < 6; ++i) {
        acc[i].x += __shfl_xor_sync(0xffffffffu, acc[i].x, 8);
        acc[i].y += __shfl_xor_sync(0xffffffffu, acc[i].y, 8);
        acc[i].x += __shfl_xor_sync(0xffffffffu, acc[i].x, 16);
        acc[i].y += __shfl_xor_sync(0xffffffffu, acc[i].y, 16);
    }

    if (lane < 8) {
        float* hrow = g_h + (size_t)warp * DD;
#pragma unroll
        for (int sg = 0; sg < 3; ++sg) {
            int off = sg * 32 + sub * 4;
            float4 hv = *(float4*)&hrow[off];
            float4 bv = *(const float4*)&b[off];
            float2 a0 = acc[2 * sg];
            float2 a1 = acc[2 * sg + 1];
            hv.x = fmaxf(SMOOTH * hv.x + (1.f - SMOOTH) * (a0.x + bv.x), 0.f);
            hv.y = fmaxf(SMOOTH * hv.y + (1.f - SMOOTH) * (a0.y + bv.y), 0.f);
            hv.z = fmaxf(SMOOTH * hv.z + (1.f - SMOOTH) * (a1.x + bv.z), 0.f);
            hv.w = fmaxf(SMOOTH * hv.w + (1.f - SMOOTH) * (a1.y + bv.w), 0.f);
            *(float4*)&hrow[off] = hv;
            __half2 p0 = __floats2half2_rn(hv.x, hv.y);
            __half2 p1 = __floats2half2_rn(hv.z, hv.w);
            uint2 u; u.x = *(unsigned*)&p0; u.y = *(unsigned*)&p1;
            *(uint2*)&g_h16[(size_t)warp * DD + off] = u;
        }
    }
}

// ---------------- final: logits + log_softmax; re-zero counts for next replay
__global__ void __launch_bounds__(256) out_kernel(const float* __restrict__ Wl,
                                                  float* __restrict__ out) {
    __shared__ float Ws2[DD * CC];
    __shared__ float Hs[32 * DD];
    __shared__ float Ls[32 * CC];
    int tid = threadIdx.x;
    int row0 = blockIdx.x * 32;

    int gz = blockIdx.x * blockDim.x + tid;
    if (gz < NN) g_count[gz] = 0;

    for (int i = tid; i < DD * CC; i += 256) Ws2[i] = Wl[i];
    for (int i = tid; i < 32 * DD; i += 256) {
        int r = row0 + i / DD;
        Hs[i] = (r < NN) ? g_h[r * DD + (i % DD)] : 0.f;
    }
    __syncthreads();

    for (int o = tid; o < 32 * CC; o += 256) {
        int r = o / CC, c = o % CC;
        float a = 0.f;
#pragma unroll 4
        for (int k = 0; k < DD; ++k) a += Hs[r * DD + k] * Ws2[k * CC + c];
        Ls[o] = a;
    }
    __syncthreads();

    if (tid < 32) {
        int r = row0 + tid;
        if (r < NN) {
            float m = -1e30f;
#pragma unroll
            for (int c = 0; c < CC; ++c) m = fmaxf(m, Ls[tid * CC + c]);
            float s = 0.f;
#pragma unroll
            for (int c = 0; c < CC; ++c) s += expf(Ls[tid * CC + c] - m);
            float lse = m + logf(s);
#pragma unroll
            for (int c = 0; c < CC; ++c) out[r * CC + c] = Ls[tid * CC + c] - lse;
        }
    }
}

// ---------------- launch ------------------------------------------------------
extern "C" void kernel_launch(void* const* d_in, const int* in_sizes, int n_in,
                              void* d_out, int out_size) {
    (void)in_sizes; (void)n_in; (void)out_size;
    const float* x    = (const float*)d_in[0];
    const int*   erow = (const int*)d_in[1];
    const int*   ecol = (const int*)d_in[2];
    const float* ev   = (const float*)d_in[3];
    const float* Wgc  = (const float*)d_in[4];
    const float* bgc  = (const float*)d_in[5];
    const float* Wlin = (const float*)d_in[6];
    float* out = (float*)d_out;

    init_hist_kernel<<<(NN * DD + 255) / 256, 256>>>(x, Wgc, erow);
    scan_kernel<<<1, 1024>>>();
    fill_kernel<<<(EE + 255) / 256, 256>>>(erow, ecol, ev);

    for (int it = 0; it < NITE; ++it) {
        gemm_kernel<<<(NBANDS + 7) / 8, 256>>>();
        agg_kernel<<<(NN * 32 + 255) / 256, 256>>>(bgc);
    }

    out_kernel<<<(NN + 31) / 32, 256>>>(Wlin, out);
}

// round 12
// speedup vs baseline: 1.1432x; 1.0725x over previous
#include <cuda_runtime.h>
#include <cuda_fp16.h>
#include <math.h>
#include <mma.h>
using namespace nvcuda;

#define NN 50000
#define EE 800000
#define DD 96
#define CC 40
#define NITE 8
#define SMOOTH 0.5f

#define NBANDS ((NN + 15) / 16)   // 3125 (NN % 16 == 0)
#define LDW 104                   // padded half ld for W smem
#define LDO 104                   // padded half ld for epilogue staging

// ---------------- scratch (device globals; no allocation allowed) ------------
__device__ float         g_h[NN * DD];          // fp32 master features
__device__ __half        g_h16[NN * DD];        // fp16 mirror (tensor-core A)
__device__ __half        g_W16[DD * DD];        // fp16 W_gc
__device__ unsigned char g_support8[NN * DD];   // e4m3 support (gather source)
__device__ int           g_count[NN];           // zeroed invariant (see out_kernel)
__device__ int           g_rowstart[NN + 1];
__device__ int           g_fill[NN];
__device__ unsigned      g_edge[EE];            // packed: col(u16) | fp16 val << 16

// packed f32x2 FMA
__device__ __forceinline__ void ffma2f(float2& d, float2 a, float2 b) {
    unsigned long long dd = *(unsigned long long*)&d;
    asm("fma.rn.f32x2 %0, %1, %2, %0;"
        : "+l"(dd) : "l"(*(unsigned long long*)&a), "l"(*(unsigned long long*)&b));
    d = *(float2*)&dd;
}

// 4x e4m3 (u32) -> two float2
__device__ __forceinline__ void fp8x4_to_f2(unsigned u, float2& f0, float2& f1) {
    unsigned h2a, h2b;
    asm("{ .reg .b16 lo, hi;\n"
        "  mov.b32 {lo, hi}, %2;\n"
        "  cvt.rn.f16x2.e4m3x2 %0, lo;\n"
        "  cvt.rn.f16x2.e4m3x2 %1, hi;\n}"
        : "=r"(h2a), "=r"(h2b) : "r"(u));
    f0 = __half22float2(*(__half2*)&h2a);
    f1 = __half22float2(*(__half2*)&h2b);
}

// two f16x2 (4 halves) -> 4x e4m3 packed u32
__device__ __forceinline__ unsigned f16x4_to_fp8(unsigned h2lo, unsigned h2hi) {
    unsigned u;
    asm("{ .reg .b16 a, b;\n"
        "  cvt.rn.satfinite.e4m3x2.f16x2 a, %1;\n"
        "  cvt.rn.satfinite.e4m3x2.f16x2 b, %2;\n"
        "  mov.b32 %0, {a, b};\n}"
        : "=r"(u) : "r"(h2lo), "r"(h2hi));
    return u;
}

// ---------------- init h/h16/W16 + edge histogram (counts pre-zeroed) --------
__global__ void init_hist_kernel(const float* __restrict__ x,
                                 const float* __restrict__ W,
                                 const int* __restrict__ erow) {
    int i = blockIdx.x * blockDim.x + threadIdx.x;
    if (i < NN * DD) { float v = x[i]; g_h[i] = v; g_h16[i] = __float2half(v); }
    if (i < DD * DD) g_W16[i] = __float2half(W[i]);
    if (i < EE) atomicAdd(&g_count[erow[i]], 1);
}

__global__ void scan_kernel() {
    __shared__ int part[1024];
    const int CH = (NN + 1023) / 1024;
    int t = threadIdx.x;
    int begin = t * CH;
    int end = begin + CH; if (end > NN) end = NN;
    int s = 0;
    for (int i = begin; i < end; ++i) s += g_count[i];
    part[t] = s;
    __syncthreads();
    for (int off = 1; off < 1024; off <<= 1) {
        int v = (t >= off) ? part[t - off] : 0;
        __syncthreads();
        part[t] += v;
        __syncthreads();
    }
    int running = (t == 0) ? 0 : part[t - 1];
    for (int i = begin; i < end; ++i) {
        g_rowstart[i] = running;
        g_fill[i] = running;
        running += g_count[i];
    }
    if (t == 1023) g_rowstart[NN] = running;  // == EE
}

__global__ void fill_kernel(const int* __restrict__ erow,
                            const int* __restrict__ ecol,
                            const float* __restrict__ ev) {
    int e = blockIdx.x * blockDim.x + threadIdx.x;
    if (e < EE) {
        int r = erow[e];
        int p = atomicAdd(&g_fill[r], 1);
        __half hv = __float2half(ev[e]);
        g_edge[p] = (unsigned)ecol[e]
                  | ((unsigned)__half_as_ushort(hv) << 16);
    }
}

// ---------------- GEMM: support8 = e4m3(h16 @ W16), tensor cores -------------
// 8 warps/block, warp = 16-row band; A frags prefetched from global h16,
// fp16 accumulators staged to smem, converted to e4m3, stored as u32s.
__global__ void __launch_bounds__(256) gemm_kernel() {
    __shared__ __half Ws[DD * LDW];      // 19968 B
    __shared__ __half Os[128 * LDO];     // 26624 B (total 46592 B)
    int tid = threadIdx.x, wid = tid >> 5, lane = tid & 31;
    int band = blockIdx.x * 8 + wid;

    for (int i = tid; i < DD * DD / 8; i += 256) {
        int r = (i * 8) / DD, c = (i * 8) % DD;
        *(uint4*)&Ws[r * LDW + c] = *(const uint4*)&g_W16[r * DD + c];
    }
    __syncthreads();
    if (band >= NBANDS) return;

    wmma::fragment<wmma::matrix_a, 16, 16, 16, __half, wmma::row_major> af[6];
    const __half* Abase = g_h16 + (size_t)band * 16 * DD;
#pragma unroll
    for (int k = 0; k < 6; ++k)
        wmma::load_matrix_sync(af[k], Abase + k * 16, DD);

    wmma::fragment<wmma::accumulator, 16, 16, 16, __half> acc[6];
#pragma unroll
    for (int n = 0; n < 6; ++n) wmma::fill_fragment(acc[n], __float2half(0.f));

#pragma unroll
    for (int k = 0; k < 6; ++k) {
#pragma unroll
        for (int n = 0; n < 6; ++n) {
            wmma::fragment<wmma::matrix_b, 16, 16, 16, __half, wmma::row_major> bf;
            wmma::load_matrix_sync(bf, Ws + (k * 16) * LDW + n * 16, LDW);
            wmma::mma_sync(acc[n], af[k], bf, acc[n]);
        }
    }

    // stage band to smem, convert to e4m3, store packed u32s
    __half* Oband = Os + wid * 16 * LDO;
#pragma unroll
    for (int n = 0; n < 6; ++n)
        wmma::store_matrix_sync(Oband + n * 16, acc[n], LDO, wmma::mem_row_major);
    __syncwarp();

#pragma unroll
    for (int t = 0; t < 12; ++t) {
        int idx = lane + 32 * t;              // 0..383 : 16 rows x 24 u32
        int r = idx / 24, c = idx % 24;       // c = output u32 column (4 feats)
        int grow = band * 16 + r;
        if (grow < NN) {
            unsigned h2lo = *(unsigned*)&Oband[r * LDO + c * 4];
            unsigned h2hi = *(unsigned*)&Oband[r * LDO + c * 4 + 2];
            ((unsigned*)(g_support8 + (size_t)grow * DD))[c] = f16x4_to_fp8(h2lo, h2hi);
        }
    }
}

// ---------------- aggregation + smooth + ReLU (fp8 gathers) ------------------
// One warp per row; 4 edge-groups x 8 feature-owner lanes; u32 (4xfp8) gathers.
__global__ void __launch_bounds__(256) agg_kernel(const float* __restrict__ b) {
    int warp = (blockIdx.x * blockDim.x + threadIdx.x) >> 5;
    int lane = threadIdx.x & 31;
    if (warp >= NN) return;
    int grp = lane >> 3;
    int sub = lane & 7;

    int j0 = g_rowstart[warp];
    int j1 = g_rowstart[warp + 1];

    float2 acc[6];
#pragma unroll
    for (int i = 0; i < 6; ++i) acc[i] = make_float2(0.f, 0.f);

    for (int j = j0 + grp; j < j1; j += 4) {
        unsigned m = __ldg(&g_edge[j]);
        int col = (int)(m & 0xFFFFu);
        float v = __half2float(__ushort_as_half((unsigned short)(m >> 16)));
        float2 vv = make_float2(v, v);
        const unsigned* s = (const unsigned*)(g_support8 + (size_t)col * DD);
        unsigned d0 = __ldg(&s[sub]);
        unsigned d1 = __ldg(&s[8 + sub]);
        unsigned d2 = __ldg(&s[16 + sub]);
        float2 f0, f1;
        fp8x4_to_f2(d0, f0, f1); ffma2f(acc[0], f0, vv); ffma2f(acc[1], f1, vv);
        fp8x4_to_f2(d1, f0, f1); ffma2f(acc[2], f0, vv); ffma2f(acc[3], f1, vv);
        fp8x4_to_f2(d2, f0, f1); ffma2f(acc[4], f0, vv); ffma2f(acc[5], f1, vv);
    }

#pragma unroll
    for (int i = 0; i < 6; ++i) {
        acc[i].x += __shfl_xor_sync(0xffffffffu, acc[i].x, 8);
        acc[i].y += __shfl_xor_sync(0xffffffffu, acc[i].y, 8);
        acc[i].x += __shfl_xor_sync(0xffffffffu, acc[i].x, 16);
        acc[i].y += __shfl_xor_sync(0xffffffffu, acc[i].y, 16);
    }

    if (lane < 8) {
        float* hrow = g_h + (size_t)warp * DD;
#pragma unroll
        for (int sg = 0; sg < 3; ++sg) {
            int off = sg * 32 + sub * 4;
            float4 hv = *(float4*)&hrow[off];
            float4 bv = *(const float4*)&b[off];
            float2 a0 = acc[2 * sg];
            float2 a1 = acc[2 * sg + 1];
            hv.x = fmaxf(SMOOTH * hv.x + (1.f - SMOOTH) * (a0.x + bv.x), 0.f);
            hv.y = fmaxf(SMOOTH * hv.y + (1.f - SMOOTH) * (a0.y + bv.y), 0.f);
            hv.z = fmaxf(SMOOTH * hv.z + (1.f - SMOOTH) * (a1.x + bv.z), 0.f);
            hv.w = fmaxf(SMOOTH * hv.w + (1.f - SMOOTH) * (a1.y + bv.w), 0.f);
            *(float4*)&hrow[off] = hv;
            __half2 p0 = __floats2half2_rn(hv.x, hv.y);
            __half2 p1 = __floats2half2_rn(hv.z, hv.w);
            uint2 u; u.x = *(unsigned*)&p0; u.y = *(unsigned*)&p1;
            *(uint2*)&g_h16[(size_t)warp * DD + off] = u;
        }
    }
}

// ---------------- final: logits + log_softmax; re-zero counts for next replay
__global__ void __launch_bounds__(256) out_kernel(const float* __restrict__ Wl,
                                                  float* __restrict__ out) {
    __shared__ float Ws2[DD * CC];
    __shared__ float Hs[32 * DD];
    __shared__ float Ls[32 * CC];
    int tid = threadIdx.x;
    int row0 = blockIdx.x * 32;

    int gz = blockIdx.x * blockDim.x + tid;
    if (gz < NN) g_count[gz] = 0;

    for (int i = tid; i < DD * CC; i += 256) Ws2[i] = Wl[i];
    for (int i = tid; i < 32 * DD; i += 256) {
        int r = row0 + i / DD;
        Hs[i] = (r < NN) ? g_h[r * DD + (i % DD)] : 0.f;
    }
    __syncthreads();

    for (int o = tid; o < 32 * CC; o += 256) {
        int r = o / CC, c = o % CC;
        float a = 0.f;
#pragma unroll 4
        for (int k = 0; k < DD; ++k) a += Hs[r * DD + k] * Ws2[k * CC + c];
        Ls[o] = a;
    }
    __syncthreads();

    if (tid < 32) {
        int r = row0 + tid;
        if (r < NN) {
            float m = -1e30f;
#pragma unroll
            for (int c = 0; c < CC; ++c) m = fmaxf(m, Ls[tid * CC + c]);
            float s = 0.f;
#pragma unroll
            for (int c = 0; c < CC; ++c) s += expf(Ls[tid * CC + c] - m);
            float lse = m + logf(s);
#pragma unroll
            for (int c = 0; c < CC; ++c) out[r * CC + c] = Ls[tid * CC + c] - lse;
        }
    }
}

// ---------------- launch ------------------------------------------------------
extern "C" void kernel_launch(void* const* d_in, const int* in_sizes, int n_in,
                              void* d_out, int out_size) {
    (void)in_sizes; (void)n_in; (void)out_size;
    const float* x    = (const float*)d_in[0];
    const int*   erow = (const int*)d_in[1];
    const int*   ecol = (const int*)d_in[2];
    const float* ev   = (const float*)d_in[3];
    const float* Wgc  = (const float*)d_in[4];
    const float* bgc  = (const float*)d_in[5];
    const float* Wlin = (const float*)d_in[6];
    float* out = (float*)d_out;

    init_hist_kernel<<<(NN * DD + 255) / 256, 256>>>(x, Wgc, erow);
    scan_kernel<<<1, 1024>>>();
    fill_kernel<<<(EE + 255) / 256, 256>>>(erow, ecol, ev);

    for (int it = 0; it < NITE; ++it) {
        gemm_kernel<<<(NBANDS + 7) / 8, 256>>>();
        agg_kernel<<<(NN * 32 + 255) / 256, 256>>>(bgc);
    }

    out_kernel<<<(NN + 31) / 32, 256>>>(Wlin, out);
}

// round 13
// speedup vs baseline: 1.1452x; 1.0017x over previous
#include <cuda_runtime.h>
#include <cuda_fp16.h>
#include <math.h>
#include <mma.h>
using namespace nvcuda;

#define NN 50000
#define EE 800000
#define DD 96
#define CC 40
#define NITE 8
#define SMOOTH 0.5f

#define NBANDS ((NN + 15) / 16)   // 3125 (NN % 16 == 0)
#define LDW 104                   // padded half ld for W smem
#define LDO 104                   // padded half ld for epilogue staging

// ---------------- scratch (device globals; no allocation allowed) ------------
__device__ float         g_h[NN * DD];          // fp32 master features
__device__ __half        g_h16[NN * DD];        // fp16 mirror (tensor-core A)
__device__ __half        g_W16[DD * DD];        // fp16 W_gc
__device__ unsigned char g_support8[NN * DD];   // e4m3 support (gather source)
__device__ int           g_count[NN];           // zeroed invariant (see out_kernel)
__device__ int           g_rowstart[NN + 1];
__device__ int           g_fill[NN];
__device__ unsigned      g_edge[EE];            // packed: col(u16) | fp16 val << 16

// packed f32x2 FMA
__device__ __forceinline__ void ffma2f(float2& d, float2 a, float2 b) {
    unsigned long long dd = *(unsigned long long*)&d;
    asm("fma.rn.f32x2 %0, %1, %2, %0;"
        : "+l"(dd) : "l"(*(unsigned long long*)&a), "l"(*(unsigned long long*)&b));
    d = *(float2*)&dd;
}

// 4x e4m3 (u32) -> two float2
__device__ __forceinline__ void fp8x4_to_f2(unsigned u, float2& f0, float2& f1) {
    unsigned h2a, h2b;
    asm("{ .reg .b16 lo, hi;\n"
        "  mov.b32 {lo, hi}, %2;\n"
        "  cvt.rn.f16x2.e4m3x2 %0, lo;\n"
        "  cvt.rn.f16x2.e4m3x2 %1, hi;\n}"
        : "=r"(h2a), "=r"(h2b) : "r"(u));
    f0 = __half22float2(*(__half2*)&h2a);
    f1 = __half22float2(*(__half2*)&h2b);
}

// two f16x2 (4 halves) -> 4x e4m3 packed u32
__device__ __forceinline__ unsigned f16x4_to_fp8(unsigned h2lo, unsigned h2hi) {
    unsigned u;
    asm("{ .reg .b16 a, b;\n"
        "  cvt.rn.satfinite.e4m3x2.f16x2 a, %1;\n"
        "  cvt.rn.satfinite.e4m3x2.f16x2 b, %2;\n"
        "  mov.b32 %0, {a, b};\n}"
        : "=r"(u) : "r"(h2lo), "r"(h2hi));
    return u;
}

// ---------------- init: h = x (fp32+fp16), W16 -------------------------------
__global__ void init_kernel(const float* __restrict__ x, const float* __restrict__ W) {
    int i = blockIdx.x * blockDim.x + threadIdx.x;
    if (i < NN * DD) { float v = x[i]; g_h[i] = v; g_h16[i] = __float2half(v); }
    if (i < DD * DD) g_W16[i] = __float2half(W[i]);
}

// ---------------- CSR build (counts pre-zeroed invariant) --------------------
__global__ void hist_kernel(const int* __restrict__ erow) {
    int e = blockIdx.x * blockDim.x + threadIdx.x;
    if (e < EE) atomicAdd(&g_count[erow[e]], 1);
}

__global__ void scan_kernel() {
    __shared__ int part[1024];
    const int CH = (NN + 1023) / 1024;
    int t = threadIdx.x;
    int begin = t * CH;
    int end = begin + CH; if (end > NN) end = NN;
    int s = 0;
    for (int i = begin; i < end; ++i) s += g_count[i];
    part[t] = s;
    __syncthreads();
    for (int off = 1; off < 1024; off <<= 1) {
        int v = (t >= off) ? part[t - off] : 0;
        __syncthreads();
        part[t] += v;
        __syncthreads();
    }
    int running = (t == 0) ? 0 : part[t - 1];
    for (int i = begin; i < end; ++i) {
        g_rowstart[i] = running;
        g_fill[i] = running;
        running += g_count[i];
    }
    if (t == 1023) g_rowstart[NN] = running;  // == EE
}

__global__ void fill_kernel(const int* __restrict__ erow,
                            const int* __restrict__ ecol,
                            const float* __restrict__ ev) {
    int e = blockIdx.x * blockDim.x + threadIdx.x;
    if (e < EE) {
        int r = erow[e];
        int p = atomicAdd(&g_fill[r], 1);
        __half hv = __float2half(ev[e]);
        g_edge[p] = (unsigned)ecol[e]
                  | ((unsigned)__half_as_ushort(hv) << 16);
    }
}

// ---------------- GEMM: support8 = e4m3(h16 @ W16), tensor cores -------------
__global__ void __launch_bounds__(256) gemm_kernel() {
    __shared__ __half Ws[DD * LDW];      // 19968 B
    __shared__ __half Os[128 * LDO];     // 26624 B
    int tid = threadIdx.x, wid = tid >> 5, lane = tid & 31;
    int band = blockIdx.x * 8 + wid;

    for (int i = tid; i < DD * DD / 8; i += 256) {
        int r = (i * 8) / DD, c = (i * 8) % DD;
        *(uint4*)&Ws[r * LDW + c] = *(const uint4*)&g_W16[r * DD + c];
    }
    __syncthreads();
    if (band >= NBANDS) return;

    wmma::fragment<wmma::matrix_a, 16, 16, 16, __half, wmma::row_major> af[6];
    const __half* Abase = g_h16 + (size_t)band * 16 * DD;
#pragma unroll
    for (int k = 0; k < 6; ++k)
        wmma::load_matrix_sync(af[k], Abase + k * 16, DD);

    wmma::fragment<wmma::accumulator, 16, 16, 16, __half> acc[6];
#pragma unroll
    for (int n = 0; n < 6; ++n) wmma::fill_fragment(acc[n], __float2half(0.f));

#pragma unroll
    for (int k = 0; k < 6; ++k) {
#pragma unroll
        for (int n = 0; n < 6; ++n) {
            wmma::fragment<wmma::matrix_b, 16, 16, 16, __half, wmma::row_major> bf;
            wmma::load_matrix_sync(bf, Ws + (k * 16) * LDW + n * 16, LDW);
            wmma::mma_sync(acc[n], af[k], bf, acc[n]);
        }
    }

    __half* Oband = Os + wid * 16 * LDO;
#pragma unroll
    for (int n = 0; n < 6; ++n)
        wmma::store_matrix_sync(Oband + n * 16, acc[n], LDO, wmma::mem_row_major);
    __syncwarp();

#pragma unroll
    for (int t = 0; t < 12; ++t) {
        int idx = lane + 32 * t;              // 0..383 : 16 rows x 24 u32
        int r = idx / 24, c = idx % 24;
        int grow = band * 16 + r;
        if (grow < NN) {
            unsigned h2lo = *(unsigned*)&Oband[r * LDO + c * 4];
            unsigned h2hi = *(unsigned*)&Oband[r * LDO + c * 4 + 2];
            ((unsigned*)(g_support8 + (size_t)grow * DD))[c] = f16x4_to_fp8(h2lo, h2hi);
        }
    }
}

// ---------------- aggregation + smooth + ReLU (fp8 gathers, meta prefetch) ---
__global__ void __launch_bounds__(256) agg_kernel(const float* __restrict__ b) {
    int warp = (blockIdx.x * blockDim.x + threadIdx.x) >> 5;
    int lane = threadIdx.x & 31;
    if (warp >= NN) return;
    int grp = lane >> 3;
    int sub = lane & 7;

    int j0 = g_rowstart[warp];
    int j1 = g_rowstart[warp + 1];

    float2 acc[6];
#pragma unroll
    for (int i = 0; i < 6; ++i) acc[i] = make_float2(0.f, 0.f);

    int j = j0 + grp;
    unsigned m = (j < j1) ? __ldg(&g_edge[j]) : 0u;
    for (; j < j1; j += 4) {
        // prefetch next batch's meta before the dependent data loads
        unsigned mnext = (j + 4 < j1) ? __ldg(&g_edge[j + 4]) : 0u;
        int col = (int)(m & 0xFFFFu);
        float v = __half2float(__ushort_as_half((unsigned short)(m >> 16)));
        float2 vv = make_float2(v, v);
        const unsigned* s = (const unsigned*)(g_support8 + (size_t)col * DD);
        unsigned d0 = __ldg(&s[sub]);
        unsigned d1 = __ldg(&s[8 + sub]);
        unsigned d2 = __ldg(&s[16 + sub]);
        float2 f0, f1;
        fp8x4_to_f2(d0, f0, f1); ffma2f(acc[0], f0, vv); ffma2f(acc[1], f1, vv);
        fp8x4_to_f2(d1, f0, f1); ffma2f(acc[2], f0, vv); ffma2f(acc[3], f1, vv);
        fp8x4_to_f2(d2, f0, f1); ffma2f(acc[4], f0, vv); ffma2f(acc[5], f1, vv);
        m = mnext;
    }

#pragma unroll
    for (int i = 0; i < 6; ++i) {
        acc[i].x += __shfl_xor_sync(0xffffffffu, acc[i].x, 8);
        acc[i].y += __shfl_xor_sync(0xffffffffu, acc[i].y, 8);
        acc[i].x += __shfl_xor_sync(0xffffffffu, acc[i].x, 16);
        acc[i].y += __shfl_xor_sync(0xffffffffu, acc[i].y, 16);
    }

    if (lane < 8) {
        float* hrow = g_h + (size_t)warp * DD;
#pragma unroll
        for (int sg = 0; sg < 3; ++sg) {
            int off = sg * 32 + sub * 4;
            float4 hv = *(float4*)&hrow[off];
            float4 bv = *(const float4*)&b[off];
            float2 a0 = acc[2 * sg];
            float2 a1 = acc[2 * sg + 1];
            hv.x = fmaxf(SMOOTH * hv.x + (1.f - SMOOTH) * (a0.x + bv.x), 0.f);
            hv.y = fmaxf(SMOOTH * hv.y + (1.f - SMOOTH) * (a0.y + bv.y), 0.f);
            hv.z = fmaxf(SMOOTH * hv.z + (1.f - SMOOTH) * (a1.x + bv.z), 0.f);
            hv.w = fmaxf(SMOOTH * hv.w + (1.f - SMOOTH) * (a1.y + bv.w), 0.f);
            *(float4*)&hrow[off] = hv;
            __half2 p0 = __floats2half2_rn(hv.x, hv.y);
            __half2 p1 = __floats2half2_rn(hv.z, hv.w);
            uint2 u; u.x = *(unsigned*)&p0; u.y = *(unsigned*)&p1;
            *(uint2*)&g_h16[(size_t)warp * DD + off] = u;
        }
    }
}

// ---------------- final: logits + log_softmax; re-zero counts for next replay
__global__ void __launch_bounds__(256) out_kernel(const float* __restrict__ Wl,
                                                  float* __restrict__ out) {
    __shared__ float Ws2[DD * CC];
    __shared__ float Hs[32 * DD];
    __shared__ float Ls[32 * CC];
    int tid = threadIdx.x;
    int row0 = blockIdx.x * 32;

    int gz = blockIdx.x * blockDim.x + tid;
    if (gz < NN) g_count[gz] = 0;

    for (int i = tid; i < DD * CC; i += 256) Ws2[i] = Wl[i];
    for (int i = tid; i < 32 * DD; i += 256) {
        int r = row0 + i / DD;
        Hs[i] = (r < NN) ? g_h[r * DD + (i % DD)] : 0.f;
    }
    __syncthreads();

    for (int o = tid; o < 32 * CC; o += 256) {
        int r = o / CC, c = o % CC;
        float a = 0.f;
#pragma unroll 4
        for (int k = 0; k < DD; ++k) a += Hs[r * DD + k] * Ws2[k * CC + c];
        Ls[o] = a;
    }
    __syncthreads();

    if (tid < 32) {
        int r = row0 + tid;
        if (r < NN) {
            float m = -1e30f;
#pragma unroll
            for (int c = 0; c < CC; ++c) m = fmaxf(m, Ls[tid * CC + c]);
            float s = 0.f;
#pragma unroll
            for (int c = 0; c < CC; ++c) s += expf(Ls[tid * CC + c] - m);
            float lse = m + logf(s);
#pragma unroll
            for (int c = 0; c < CC; ++c) out[r * CC + c] = Ls[tid * CC + c] - lse;
        }
    }
}

// ---------------- launch ------------------------------------------------------
// Forked-stream capture: the CSR build (hist->scan->fill) runs concurrently
// with init + first GEMM; join before the first agg. All ops graph-capturable.
extern "C" void kernel_launch(void* const* d_in, const int* in_sizes, int n_in,
                              void* d_out, int out_size) {
    (void)in_sizes; (void)n_in; (void)out_size;
    const float* x    = (const float*)d_in[0];
    const int*   erow = (const int*)d_in[1];
    const int*   ecol = (const int*)d_in[2];
    const float* ev   = (const float*)d_in[3];
    const float* Wgc  = (const float*)d_in[4];
    const float* bgc  = (const float*)d_in[5];
    const float* Wlin = (const float*)d_in[6];
    float* out = (float*)d_out;

    cudaStream_t s2;
    cudaEvent_t evFork, evJoin;
    cudaStreamCreateWithFlags(&s2, cudaStreamNonBlocking);
    cudaEventCreateWithFlags(&evFork, cudaEventDisableTiming);
    cudaEventCreateWithFlags(&evJoin, cudaEventDisableTiming);

    // fork: CSR build on s2 (depends only on pre-zeroed g_count invariant)
    cudaEventRecord(evFork, 0);
    cudaStreamWaitEvent(s2, evFork, 0);
    hist_kernel<<<(EE + 255) / 256, 256, 0, s2>>>(erow);
    scan_kernel<<<1, 1024, 0, s2>>>();
    fill_kernel<<<(EE + 255) / 256, 256, 0, s2>>>(erow, ecol, ev);
    cudaEventRecord(evJoin, s2);

    // main stream: init + first GEMM overlap with the CSR build
    init_kernel<<<(NN * DD + 255) / 256, 256>>>(x, Wgc);
    gemm_kernel<<<(NBANDS + 7) / 8, 256>>>();
    cudaStreamWaitEvent(0, evJoin, 0);

    for (int it = 0; it < NITE; ++it) {
        if (it > 0) gemm_kernel<<<(NBANDS + 7) / 8, 256>>>();
        agg_kernel<<<(NN * 32 + 255) / 256, 256>>>(bgc);
    }

    out_kernel<<<(NN + 31) / 32, 256>>>(Wlin, out);

    cudaEventDestroy(evFork);
    cudaEventDestroy(evJoin);
    cudaStreamDestroy(s2);
}

// round 14
// speedup vs baseline: 1.1984x; 1.0465x over previous
#include <cuda_runtime.h>
#include <cuda_fp16.h>
#include <math.h>
#include <mma.h>
using namespace nvcuda;

#define NN 50000
#define EE 800000
#define DD 96
#define CC 40
#define NITE 8
#define SMOOTH 0.5f

#define NBANDS ((NN + 15) / 16)   // 3125 (NN % 16 == 0)
#define LDW 104                   // padded half ld for W smem
#define LDO 104                   // padded half ld for epilogue staging

// ---------------- scratch (device globals; no allocation allowed) ------------
__device__ __half        g_h16[NN * DD];        // fp16 feature state (sole copy)
__device__ __half        g_W16[DD * DD];        // fp16 W_gc
__device__ unsigned char g_support8[NN * DD];   // e4m3 support (gather source)
__device__ int           g_count[NN];           // zeroed invariant (see out_kernel)
__device__ int           g_rowstart[NN + 1];
__device__ int           g_fill[NN];
__device__ unsigned      g_edge[EE];            // packed: col(u16) | fp16 val << 16

// packed f32x2 FMA
__device__ __forceinline__ void ffma2f(float2& d, float2 a, float2 b) {
    unsigned long long dd = *(unsigned long long*)&d;
    asm("fma.rn.f32x2 %0, %1, %2, %0;"
        : "+l"(dd) : "l"(*(unsigned long long*)&a), "l"(*(unsigned long long*)&b));
    d = *(float2*)&dd;
}

// 4x e4m3 (u32) -> two float2
__device__ __forceinline__ void fp8x4_to_f2(unsigned u, float2& f0, float2& f1) {
    unsigned h2a, h2b;
    asm("{ .reg .b16 lo, hi;\n"
        "  mov.b32 {lo, hi}, %2;\n"
        "  cvt.rn.f16x2.e4m3x2 %0, lo;\n"
        "  cvt.rn.f16x2.e4m3x2 %1, hi;\n}"
        : "=r"(h2a), "=r"(h2b) : "r"(u));
    f0 = __half22float2(*(__half2*)&h2a);
    f1 = __half22float2(*(__half2*)&h2b);
}

// two f16x2 (4 halves) -> 4x e4m3 packed u32
__device__ __forceinline__ unsigned f16x4_to_fp8(unsigned h2lo, unsigned h2hi) {
    unsigned u;
    asm("{ .reg .b16 a, b;\n"
        "  cvt.rn.satfinite.e4m3x2.f16x2 a, %1;\n"
        "  cvt.rn.satfinite.e4m3x2.f16x2 b, %2;\n"
        "  mov.b32 %0, {a, b};\n}"
        : "=r"(u) : "r"(h2lo), "r"(h2hi));
    return u;
}

// ---------------- init: h16 = fp16(x) (vectorized), W16 ----------------------
// one thread per 8 elements: 2x float4 load -> 1x uint4 (8 halves) store
__global__ void init_kernel(const float* __restrict__ x, const float* __restrict__ W) {
    int i = blockIdx.x * blockDim.x + threadIdx.x;
    if (i < NN * DD / 8) {
        float4 a = *(const float4*)&x[i * 8];
        float4 c = *(const float4*)&x[i * 8 + 4];
        __half2 h0 = __floats2half2_rn(a.x, a.y);
        __half2 h1 = __floats2half2_rn(a.z, a.w);
        __half2 h2 = __floats2half2_rn(c.x, c.y);
        __half2 h3 = __floats2half2_rn(c.z, c.w);
        uint4 u;
        u.x = *(unsigned*)&h0; u.y = *(unsigned*)&h1;
        u.z = *(unsigned*)&h2; u.w = *(unsigned*)&h3;
        *(uint4*)&g_h16[i * 8] = u;
    }
    if (i < DD * DD) g_W16[i] = __float2half(W[i]);
}

// ---------------- CSR build (counts pre-zeroed invariant) --------------------
__global__ void hist_kernel(const int* __restrict__ erow) {
    int e = blockIdx.x * blockDim.x + threadIdx.x;
    if (e < EE) atomicAdd(&g_count[erow[e]], 1);
}

__global__ void scan_kernel() {
    __shared__ int part[1024];
    const int CH = (NN + 1023) / 1024;
    int t = threadIdx.x;
    int begin = t * CH;
    int end = begin + CH; if (end > NN) end = NN;
    int s = 0;
    for (int i = begin; i < end; ++i) s += g_count[i];
    part[t] = s;
    __syncthreads();
    for (int off = 1; off < 1024; off <<= 1) {
        int v = (t >= off) ? part[t - off] : 0;
        __syncthreads();
        part[t] += v;
        __syncthreads();
    }
    int running = (t == 0) ? 0 : part[t - 1];
    for (int i = begin; i < end; ++i) {
        g_rowstart[i] = running;
        g_fill[i] = running;
        running += g_count[i];
    }
    if (t == 1023) g_rowstart[NN] = running;  // == EE
}

__global__ void fill_kernel(const int* __restrict__ erow,
                            const int* __restrict__ ecol,
                            const float* __restrict__ ev) {
    int e = blockIdx.x * blockDim.x + threadIdx.x;
    if (e < EE) {
        int r = erow[e];
        int p = atomicAdd(&g_fill[r], 1);
        __half hv = __float2half(ev[e]);
        g_edge[p] = (unsigned)ecol[e]
                  | ((unsigned)__half_as_ushort(hv) << 16);
    }
}

// ---------------- GEMM: support8 = e4m3(h16 @ W16), tensor cores -------------
__global__ void __launch_bounds__(256) gemm_kernel() {
    __shared__ __half Ws[DD * LDW];      // 19968 B
    __shared__ __half Os[128 * LDO];     // 26624 B
    int tid = threadIdx.x, wid = tid >> 5, lane = tid & 31;
    int band = blockIdx.x * 8 + wid;

    for (int i = tid; i < DD * DD / 8; i += 256) {
        int r = (i * 8) / DD, c = (i * 8) % DD;
        *(uint4*)&Ws[r * LDW + c] = *(const uint4*)&g_W16[r * DD + c];
    }
    __syncthreads();
    if (band >= NBANDS) return;

    wmma::fragment<wmma::matrix_a, 16, 16, 16, __half, wmma::row_major> af[6];
    const __half* Abase = g_h16 + (size_t)band * 16 * DD;
#pragma unroll
    for (int k = 0; k < 6; ++k)
        wmma::load_matrix_sync(af[k], Abase + k * 16, DD);

    wmma::fragment<wmma::accumulator, 16, 16, 16, __half> acc[6];
#pragma unroll
    for (int n = 0; n < 6; ++n) wmma::fill_fragment(acc[n], __float2half(0.f));

#pragma unroll
    for (int k = 0; k < 6; ++k) {
#pragma unroll
        for (int n = 0; n < 6; ++n) {
            wmma::fragment<wmma::matrix_b, 16, 16, 16, __half, wmma::row_major> bf;
            wmma::load_matrix_sync(bf, Ws + (k * 16) * LDW + n * 16, LDW);
            wmma::mma_sync(acc[n], af[k], bf, acc[n]);
        }
    }

    __half* Oband = Os + wid * 16 * LDO;
#pragma unroll
    for (int n = 0; n < 6; ++n)
        wmma::store_matrix_sync(Oband + n * 16, acc[n], LDO, wmma::mem_row_major);
    __syncwarp();

#pragma unroll
    for (int t = 0; t < 12; ++t) {
        int idx = lane + 32 * t;              // 0..383 : 16 rows x 24 u32
        int r = idx / 24, c = idx % 24;
        int grow = band * 16 + r;
        if (grow < NN) {
            unsigned h2lo = *(unsigned*)&Oband[r * LDO + c * 4];
            unsigned h2hi = *(unsigned*)&Oband[r * LDO + c * 4 + 2];
            ((unsigned*)(g_support8 + (size_t)grow * DD))[c] = f16x4_to_fp8(h2lo, h2hi);
        }
    }
}

// ---------------- aggregation + smooth + ReLU (fp8 gathers, fp16 state) ------
__global__ void __launch_bounds__(256) agg_kernel(const float* __restrict__ b) {
    int warp = (blockIdx.x * blockDim.x + threadIdx.x) >> 5;
    int lane = threadIdx.x & 31;
    if (warp >= NN) return;
    int grp = lane >> 3;
    int sub = lane & 7;

    int j0 = g_rowstart[warp];
    int j1 = g_rowstart[warp + 1];

    float2 acc[6];
#pragma unroll
    for (int i = 0; i < 6; ++i) acc[i] = make_float2(0.f, 0.f);

    for (int j = j0 + grp; j < j1; j += 4) {
        unsigned m = __ldg(&g_edge[j]);
        int col = (int)(m & 0xFFFFu);
        float v = __half2float(__ushort_as_half((unsigned short)(m >> 16)));
        float2 vv = make_float2(v, v);
        const unsigned* s = (const unsigned*)(g_support8 + (size_t)col * DD);
        unsigned d0 = __ldg(&s[sub]);
        unsigned d1 = __ldg(&s[8 + sub]);
        unsigned d2 = __ldg(&s[16 + sub]);
        float2 f0, f1;
        fp8x4_to_f2(d0, f0, f1); ffma2f(acc[0], f0, vv); ffma2f(acc[1], f1, vv);
        fp8x4_to_f2(d1, f0, f1); ffma2f(acc[2], f0, vv); ffma2f(acc[3], f1, vv);
        fp8x4_to_f2(d2, f0, f1); ffma2f(acc[4], f0, vv); ffma2f(acc[5], f1, vv);
    }

#pragma unroll
    for (int i = 0; i < 6; ++i) {
        acc[i].x += __shfl_xor_sync(0xffffffffu, acc[i].x, 8);
        acc[i].y += __shfl_xor_sync(0xffffffffu, acc[i].y, 8);
        acc[i].x += __shfl_xor_sync(0xffffffffu, acc[i].x, 16);
        acc[i].y += __shfl_xor_sync(0xffffffffu, acc[i].y, 16);
    }

    if (lane < 8) {
        __half* hrow = g_h16 + (size_t)warp * DD;
#pragma unroll
        for (int sg = 0; sg < 3; ++sg) {
            int off = sg * 32 + sub * 4;
            uint2 hu = *(uint2*)&hrow[off];
            float2 h0 = __half22float2(*(__half2*)&hu.x);
            float2 h1 = __half22float2(*(__half2*)&hu.y);
            float4 bv = *(const float4*)&b[off];
            float2 a0 = acc[2 * sg];
            float2 a1 = acc[2 * sg + 1];
            float r0 = fmaxf(SMOOTH * h0.x + (1.f - SMOOTH) * (a0.x + bv.x), 0.f);
            float r1 = fmaxf(SMOOTH * h0.y + (1.f - SMOOTH) * (a0.y + bv.y), 0.f);
            float r2 = fmaxf(SMOOTH * h1.x + (1.f - SMOOTH) * (a1.x + bv.z), 0.f);
            float r3 = fmaxf(SMOOTH * h1.y + (1.f - SMOOTH) * (a1.y + bv.w), 0.f);
            __half2 p0 = __floats2half2_rn(r0, r1);
            __half2 p1 = __floats2half2_rn(r2, r3);
            uint2 u; u.x = *(unsigned*)&p0; u.y = *(unsigned*)&p1;
            *(uint2*)&hrow[off] = u;
        }
    }
}

// ---------------- final: logits + log_softmax; re-zero counts for next replay
__global__ void __launch_bounds__(256) out_kernel(const float* __restrict__ Wl,
                                                  float* __restrict__ out) {
    __shared__ float Ws2[DD * CC];
    __shared__ float Hs[32 * DD];
    __shared__ float Ls[32 * CC];
    int tid = threadIdx.x;
    int row0 = blockIdx.x * 32;

    int gz = blockIdx.x * blockDim.x + tid;
    if (gz < NN) g_count[gz] = 0;

    for (int i = tid; i < DD * CC; i += 256) Ws2[i] = Wl[i];
    for (int i = tid; i < 32 * DD; i += 256) {
        int r = row0 + i / DD;
        Hs[i] = (r < NN) ? __half2float(g_h16[(size_t)r * DD + (i % DD)]) : 0.f;
    }
    __syncthreads();

    for (int o = tid; o < 32 * CC; o += 256) {
        int r = o / CC, c = o % CC;
        float a = 0.f;
#pragma unroll 4
        for (int k = 0; k < DD; ++k) a += Hs[r * DD + k] * Ws2[k * CC + c];
        Ls[o] = a;
    }
    __syncthreads();

    if (tid < 32) {
        int r = row0 + tid;
        if (r < NN) {
            float m = -1e30f;
#pragma unroll
            for (int c = 0; c < CC; ++c) m = fmaxf(m, Ls[tid * CC + c]);
            float s = 0.f;
#pragma unroll
            for (int c = 0; c < CC; ++c) s += expf(Ls[tid * CC + c] - m);
            float lse = m + logf(s);
#pragma unroll
            for (int c = 0; c < CC; ++c) out[r * CC + c] = Ls[tid * CC + c] - lse;
        }
    }
}

// ---------------- launch ------------------------------------------------------
// Forked-stream capture: CSR build runs concurrently with init + first GEMM.
extern "C" void kernel_launch(void* const* d_in, const int* in_sizes, int n_in,
                              void* d_out, int out_size) {
    (void)in_sizes; (void)n_in; (void)out_size;
    const float* x    = (const float*)d_in[0];
    const int*   erow = (const int*)d_in[1];
    const int*   ecol = (const int*)d_in[2];
    const float* ev   = (const float*)d_in[3];
    const float* Wgc  = (const float*)d_in[4];
    const float* bgc  = (const float*)d_in[5];
    const float* Wlin = (const float*)d_in[6];
    float* out = (float*)d_out;

    cudaStream_t s2;
    cudaEvent_t evFork, evJoin;
    cudaStreamCreateWithFlags(&s2, cudaStreamNonBlocking);
    cudaEventCreateWithFlags(&evFork, cudaEventDisableTiming);
    cudaEventCreateWithFlags(&evJoin, cudaEventDisableTiming);

    cudaEventRecord(evFork, 0);
    cudaStreamWaitEvent(s2, evFork, 0);
    hist_kernel<<<(EE + 255) / 256, 256, 0, s2>>>(erow);
    scan_kernel<<<1, 1024, 0, s2>>>();
    fill_kernel<<<(EE + 255) / 256, 256, 0, s2>>>(erow, ecol, ev);
    cudaEventRecord(evJoin, s2);

    init_kernel<<<(NN * DD / 8 + 255) / 256, 256>>>(x, Wgc);
    gemm_kernel<<<(NBANDS + 7) / 8, 256>>>();
    cudaStreamWaitEvent(0, evJoin, 0);

    for (int it = 0; it < NITE; ++it) {
        if (it > 0) gemm_kernel<<<(NBANDS + 7) / 8, 256>>>();
        agg_kernel<<<(NN * 32 + 255) / 256, 256>>>(bgc);
    }

    out_kernel<<<(NN + 31) / 32, 256>>>(Wlin, out);

    cudaEventDestroy(evFork);
    cudaEventDestroy(evJoin);
    cudaStreamDestroy(s2);
}